// round 11
// baseline (speedup 1.0000x reference)
#include <cuda_runtime.h>
#include <cuda_fp16.h>
#include <cstdint>
#include <math.h>

// ============================================================================
// Fused NeRF MLP (RadianceField), base sm_100 target (no tcgen05).
// fp16 mma.sync.m16n8k16 (fp32 accum) + ldmatrix.x4.
// 2 CTAs/SM x 256 threads, 64-row tiles: independent CTAs overlap each
// other's barrier/epilogue gaps on the tensor pipe. Weights pre-converted to
// fp16, streamed in 64-k chunks through a per-CTA 2-slot cp.async ring.
// ============================================================================

#define NTHREADS 256
#define MTILE    64

// SMEM map (bytes) per CTA
#define ACT_OFF  0                     // 64 rows x 512B (256 half cols), swizzled
#define XB_OFF   32768                 // 64 rows x 256B (128 half cols), swizzled
#define WB_OFF   49152                 // 2 x 32768 weight chunk ring
#define WB_BYTES 32768                 // slot: 256 rows x 128B
#define SMEM_TOTAL (WB_OFF + 2 * WB_BYTES)   // 114688 -> 2 CTAs = 229376/SM

#define NCHUNKS  45
#define WH_TOTAL 647168

struct Params { const float* p[32]; };

__constant__ int c_widx[13] = {2, 4, 6, 8, 10, 12, 14, 16, 20, 22, 24, 26, 28};
__constant__ int c_kact[13] = {63, 256, 256, 256, 256, 319, 256, 256, 256, 283, 128, 128, 128};
__constant__ int c_kpad[13] = {64, 256, 256, 256, 256, 320, 256, 256, 256, 320, 128, 128, 128};
__constant__ int c_nch [13] = { 1,   4,   4,   4,   4,   5,   4,   4,   4,   5,   2,   2,   2};
__constant__ int c_woff[13] = {0, 16384, 81920, 147456, 212992, 278528, 360448,
                               425984, 491520, 557056, 598016, 614400, 630784};
// flat chunk tables (45 chunks of 64 k-cols)
__constant__ int ck_li[NCHUNKS] = {0,
    1,1,1,1, 2,2,2,2, 3,3,3,3, 4,4,4,4,
    5,5,5,5,5, 6,6,6,6, 7,7,7,7, 8,8,8,8,
    9,9,9,9,9, 10,10, 11,11, 12,12};
__constant__ int ck_c [NCHUNKS] = {0,
    0,1,2,3, 0,1,2,3, 0,1,2,3, 0,1,2,3,
    0,1,2,3,4, 0,1,2,3, 0,1,2,3, 0,1,2,3,
    0,1,2,3,4, 0,1, 0,1, 0,1};

// fp16 weights, per-layer row-major [n][Kpad] (zero-padded)
__device__ __align__(16) __half g_wh[WH_TOTAL];

// ----------------------------------------------------------------------------
__device__ __forceinline__ uint32_t smem_u32_of(const void* p) {
    uint32_t a;
    asm("{ .reg .u64 t; cvta.to.shared.u64 t, %1; cvt.u32.u64 %0, t; }" : "=r"(a) : "l"(p));
    return a;
}
__device__ __forceinline__ void cp_async16(uint32_t dst, const void* src) {
    asm volatile("cp.async.cg.shared.global [%0], [%1], 16;" :: "r"(dst), "l"(src));
}
__device__ __forceinline__ void cp_commit() { asm volatile("cp.async.commit_group;"); }
template <int N> __device__ __forceinline__ void cp_wait() {
    asm volatile("cp.async.wait_group %0;" :: "n"(N));
}
__device__ __forceinline__ void ldsm_x4(uint32_t r[4], uint32_t addr) {
    asm volatile("ldmatrix.sync.aligned.m8n8.x4.shared.b16 {%0,%1,%2,%3}, [%4];"
                 : "=r"(r[0]), "=r"(r[1]), "=r"(r[2]), "=r"(r[3]) : "r"(addr));
}
__device__ __forceinline__ void mma_f16(float c[4], uint32_t a0, uint32_t a1,
                                        uint32_t a2, uint32_t a3,
                                        uint32_t b0, uint32_t b1) {
    asm volatile(
        "mma.sync.aligned.m16n8k16.row.col.f32.f16.f16.f32 "
        "{%0,%1,%2,%3}, {%4,%5,%6,%7}, {%8,%9}, {%0,%1,%2,%3};"
        : "+f"(c[0]), "+f"(c[1]), "+f"(c[2]), "+f"(c[3])
        : "r"(a0), "r"(a1), "r"(a2), "r"(a3), "r"(b0), "r"(b1));
}
__device__ __forceinline__ void sts32(uint32_t addr, uint32_t v) {
    asm volatile("st.shared.b32 [%0], %1;" :: "r"(addr), "r"(v));
}
__device__ __forceinline__ void sts128(uint32_t addr, uint32_t a, uint32_t b,
                                       uint32_t c, uint32_t d) {
    asm volatile("st.shared.v4.b32 [%0], {%1,%2,%3,%4};"
                 :: "r"(addr), "r"(a), "r"(b), "r"(c), "r"(d));
}
__device__ __forceinline__ uint4 lds128(uint32_t addr) {
    uint4 u;
    asm volatile("ld.shared.v4.b32 {%0,%1,%2,%3}, [%4];"
                 : "=r"(u.x), "=r"(u.y), "=r"(u.z), "=r"(u.w) : "r"(addr));
    return u;
}
__device__ __forceinline__ uint32_t h2u(__half2 h) { return *(uint32_t*)&h; }

// ============================================================================
// Prepass: fp32 weights -> fp16, zero-padded, per-layer [n][Kpad] row-major
// ============================================================================
__global__ void wconv_kernel(Params P) {
    int i = blockIdx.x * blockDim.x + threadIdx.x;
    if (i >= WH_TOTAL) return;
    int li = 0;
#pragma unroll
    for (int l = 1; l < 13; l++) if (i >= c_woff[l]) li = l;
    int e = i - c_woff[li];
    int Kp = c_kpad[li];
    int n = e / Kp;
    int k = e - n * Kp;
    int Kact = c_kact[li];
    float v = (k < Kact) ? __ldg(P.p[c_widx[li]] + (size_t)n * Kact + k) : 0.0f;
    g_wh[i] = __float2half_rn(v);
}

// ============================================================================
// Weight chunk issue into ring slot. Row n = 128B (8 granules),
// granules XOR-swizzled by (n&7).
// ============================================================================
__device__ __forceinline__ void issue_chunk(int idx, uint32_t slot, int tid) {
    const int li = ck_li[idx], c = ck_c[idx];
    const int N = (li < 9) ? 256 : 128;
    const int Kp = c_kpad[li];
    const __half* __restrict__ base = g_wh + c_woff[li] + c * 64;
    const int tot = N * 8;                  // granules
#pragma unroll 4
    for (int f = tid; f < tot; f += NTHREADS) {
        int n = f >> 3, g = f & 7;
        cp_async16(slot + (uint32_t)(n * 128 + ((g ^ (n & 7)) << 4)),
                   base + (size_t)n * Kp + g * 8);
    }
    cp_commit();
}

// ============================================================================
// Compute one 64-k chunk (4 k-steps of 16). Warp (wm, wn):
// rows [wm*32,+32), cols [wn*NT*8, +NT*8). XBSRC: A from XB (256B rows).
// ============================================================================
template <int NT, bool XBSRC>
__device__ __forceinline__ void compute_chunk(float acc[2][8][4], uint32_t abase, int cb,
                                              uint32_t wb, int lane, int wm, int wn) {
    const int arow = lane & 15;
    const int asel = lane >> 4;
    const int brow = lane & 7;
    const int bsel = (lane >> 3) & 1;
    const int bnto = lane >> 4;
    const int RS = XBSRC ? 256 : 512;
    const uint32_t a_base = abase + (uint32_t)((wm * 32 + arow) * RS);
    const int sA = arow & 7;
    const int cbb = (cb >> 3) + asel;
#pragma unroll
    for (int ks = 0; ks < 4; ks++) {
        uint32_t b0[NT], b1[NT];
#pragma unroll
        for (int p = 0; p < NT / 2; p++) {
            int n = wn * (NT * 8) + (2 * p + bnto) * 8 + brow;
            int gr = ks * 2 + bsel;
            uint32_t q[4];
            ldsm_x4(q, wb + (uint32_t)(n * 128 + ((gr ^ (n & 7)) << 4)));
            b0[2 * p] = q[0]; b1[2 * p] = q[1];
            b0[2 * p + 1] = q[2]; b1[2 * p + 1] = q[3];
        }
#pragma unroll
        for (int mt = 0; mt < 2; mt++) {
            uint32_t a[4];
            int gr = cbb + ks * 2;
            ldsm_x4(a, a_base + (uint32_t)(mt * 16 * RS + ((gr ^ sA) << 4)));
#pragma unroll
            for (int nt = 0; nt < NT; nt++)
                mma_f16(acc[mt][nt], a[0], a[1], a[2], a[3], b0[nt], b1[nt]);
        }
    }
}

template <int NT>
__device__ __forceinline__ void zero_acc(float acc[2][8][4]) {
#pragma unroll
    for (int m = 0; m < 2; m++)
#pragma unroll
        for (int n = 0; n < NT; n++)
#pragma unroll
            for (int q = 0; q < 4; q++) acc[m][n][q] = 0.0f;
}

template <int NT>
__device__ __forceinline__ void epilogue(float acc[2][8][4], uint32_t act_u,
                                         const float* __restrict__ bb, bool relu,
                                         int lane, int wm, int wn) {
#pragma unroll
    for (int mt = 0; mt < 2; mt++) {
        int row0 = wm * 32 + mt * 16 + (lane >> 2);
        int row1 = row0 + 8;
#pragma unroll
        for (int nt = 0; nt < NT; nt++) {
            int col0 = wn * (NT * 8) + nt * 8 + 2 * (lane & 3);
            float2 bv = __ldg((const float2*)(bb + col0));
            float v0 = acc[mt][nt][0] + bv.x;
            float v1 = acc[mt][nt][1] + bv.y;
            float v2 = acc[mt][nt][2] + bv.x;
            float v3 = acc[mt][nt][3] + bv.y;
            if (relu) {
                v0 = fmaxf(v0, 0.0f); v1 = fmaxf(v1, 0.0f);
                v2 = fmaxf(v2, 0.0f); v3 = fmaxf(v3, 0.0f);
            }
            int g = col0 >> 3, cb2 = (col0 & 7) * 2;
            sts32(act_u + (uint32_t)(row0 * 512 + ((g ^ (row0 & 7)) << 4) + cb2),
                  h2u(__floats2half2_rn(v0, v1)));
            sts32(act_u + (uint32_t)(row1 * 512 + ((g ^ (row1 & 7)) << 4) + cb2),
                  h2u(__floats2half2_rn(v2, v3)));
        }
    }
}

// ============================================================================
// Kernel
// ============================================================================
__global__ void __launch_bounds__(NTHREADS, 2)
nerf_fused_fp16(Params P, float* __restrict__ out, int ntiles, int Btot) {
    extern __shared__ __align__(1024) char sm[];
    const uint32_t sb = smem_u32_of(sm);
    const uint32_t act_u = sb + ACT_OFF;
    const uint32_t xb_u  = sb + XB_OFF;
    const uint32_t wb_u  = sb + WB_OFF;

    const int tid = threadIdx.x;
    const int lane = tid & 31;
    const int w = tid >> 5;
    const int wm = w >> 2;     // 0..1 (32-row half)
    const int wn = w & 3;      // 0..3 (col slice)

    const float* __restrict__ xin  = P.p[0];
    const float* __restrict__ ddir = P.p[1];
    const float* __restrict__ wsig = P.p[18];
    const float  bsig = __ldg(P.p[19]);
    const float* __restrict__ wrgb = P.p[30];
    const float* __restrict__ brgb = P.p[31];

    float acc[2][8][4];

    for (int tile = blockIdx.x; tile < ntiles; tile += gridDim.x) {
        __syncthreads();   // prev tile fully done

        // ---- prologue: issue chunk 0 into slot 0
        issue_chunk(0, wb_u, tid);

        // ---- x -> XB (fp16, swizzled); cols 0..62 = x, 63..127 = 0
        {
            int r = tid >> 2, sel = tid & 3;
            const float* xr = xin + ((size_t)tile * MTILE + r) * 63;
#pragma unroll
            for (int gi = 0; gi < 4; gi++) {
                int g = sel * 4 + gi;
                int c0 = g * 8;
                uint32_t u[4];
#pragma unroll
                for (int q = 0; q < 4; q++) {
                    int c = c0 + q * 2;
                    float f0 = (c < 63) ? __ldg(xr + c) : 0.0f;
                    float f1 = (c + 1 < 63) ? __ldg(xr + c + 1) : 0.0f;
                    u[q] = h2u(__floats2half2_rn(f0, f1));
                }
                sts128(xb_u + (uint32_t)(r * 256 + ((g ^ (r & 7)) << 4)),
                       u[0], u[1], u[2], u[3]);
            }
        }

        int gc = 0;
        for (int li = 0; li < 13; li++) {
            const int nch = c_nch[li];
            const bool n256 = (li < 9);
            const float* __restrict__ bb = P.p[c_widx[li] + 1];

            if (n256) zero_acc<8>(acc); else zero_acc<4>(acc);

            for (int c = 0; c < nch; c++) {
                cp_wait<0>();      // this chunk's data arrived (per-thread)
                __syncthreads();   // visible to all; all warps done w/ gc-1

                if (gc + 1 < NCHUNKS)
                    issue_chunk(gc + 1, wb_u + ((gc + 1) & 1) * WB_BYTES, tid);

                const uint32_t wb = wb_u + (gc & 1) * WB_BYTES;
                bool xbs = (li == 0) || ((li == 5 || li == 9) && c == 4);
                if (n256) {
                    if (xbs) compute_chunk<8, true >(acc, xb_u, 0, wb, lane, wm, wn);
                    else     compute_chunk<8, false>(acc, act_u, c * 64, wb, lane, wm, wn);
                } else {
                    if (xbs) compute_chunk<4, true >(acc, xb_u, 0, wb, lane, wm, wn);
                    else     compute_chunk<4, false>(acc, act_u, c * 64, wb, lane, wm, wn);
                }
                gc++;
            }

            __syncthreads();   // all reads of ACT/XB for this layer done
            if (n256) epilogue<8>(acc, act_u, bb, li != 8, lane, wm, wn);
            else      epilogue<4>(acc, act_u, bb, li != 8, lane, wm, wn);

            if (li == 5) {
                // d -> XB (x is dead): cols 0..26 = d, rest 0
                int r = tid >> 2, sel = tid & 3;
                const float* dr = ddir + ((size_t)tile * MTILE + r) * 27;
#pragma unroll
                for (int gi = 0; gi < 4; gi++) {
                    int g = sel * 4 + gi;
                    int c0 = g * 8;
                    uint32_t u[4];
#pragma unroll
                    for (int q = 0; q < 4; q++) {
                        int c = c0 + q * 2;
                        float f0 = (c < 27) ? __ldg(dr + c) : 0.0f;
                        float f1 = (c + 1 < 27) ? __ldg(dr + c + 1) : 0.0f;
                        u[q] = h2u(__floats2half2_rn(f0, f1));
                    }
                    sts128(xb_u + (uint32_t)(r * 256 + ((g ^ (r & 7)) << 4)),
                           u[0], u[1], u[2], u[3]);
                }
            }

            if (li == 7) {
                __syncthreads();   // epilogue visible
                // sigma = softplus(h7 . wsig + bsig); 4 threads/row
                int r = tid >> 2, sel = tid & 3;
                float a = 0.0f;
#pragma unroll
                for (int i = 0; i < 8; i++) {
                    int g = sel * 8 + i;
                    uint4 u = lds128(act_u + (uint32_t)(r * 512 + ((g ^ (r & 7)) << 4)));
                    __half2* hp = (__half2*)&u;
                    float4 w0 = __ldg((const float4*)(wsig + g * 8));
                    float4 w1 = __ldg((const float4*)(wsig + g * 8 + 4));
                    float2 f;
                    f = __half22float2(hp[0]); a += f.x * w0.x + f.y * w0.y;
                    f = __half22float2(hp[1]); a += f.x * w0.z + f.y * w0.w;
                    f = __half22float2(hp[2]); a += f.x * w1.x + f.y * w1.y;
                    f = __half22float2(hp[3]); a += f.x * w1.z + f.y * w1.w;
                }
                a += __shfl_xor_sync(0xFFFFFFFFu, a, 1);
                a += __shfl_xor_sync(0xFFFFFFFFu, a, 2);
                if (!sel) {
                    float z = a + bsig;
                    float sp = fmaxf(z, 0.0f) + log1pf(expf(-fabsf(z)));
                    out[(size_t)3 * Btot + (size_t)tile * MTILE + r] = sp;
                }
            }
            if (li == 12) {
                __syncthreads();   // epilogue visible
                // rgb = sigmoid(h12 @ Wrgb^T + brgb); 4 threads/row
                int r = tid >> 2, sel = tid & 3;
                float a0 = 0.0f, a1 = 0.0f, a2 = 0.0f;
#pragma unroll
                for (int i = 0; i < 4; i++) {
                    int g = sel * 4 + i;
                    uint4 u = lds128(act_u + (uint32_t)(r * 512 + ((g ^ (r & 7)) << 4)));
                    __half2* hp = (__half2*)&u;
                    int wo = g * 8;
                    float4 wa0 = __ldg((const float4*)(wrgb + wo));
                    float4 wa1 = __ldg((const float4*)(wrgb + wo + 4));
                    float4 wb0 = __ldg((const float4*)(wrgb + 128 + wo));
                    float4 wb1 = __ldg((const float4*)(wrgb + 128 + wo + 4));
                    float4 wc0 = __ldg((const float4*)(wrgb + 256 + wo));
                    float4 wc1 = __ldg((const float4*)(wrgb + 256 + wo + 4));
                    float2 f0 = __half22float2(hp[0]);
                    float2 f1 = __half22float2(hp[1]);
                    float2 f2 = __half22float2(hp[2]);
                    float2 f3 = __half22float2(hp[3]);
                    a0 += f0.x*wa0.x + f0.y*wa0.y + f1.x*wa0.z + f1.y*wa0.w
                        + f2.x*wa1.x + f2.y*wa1.y + f3.x*wa1.z + f3.y*wa1.w;
                    a1 += f0.x*wb0.x + f0.y*wb0.y + f1.x*wb0.z + f1.y*wb0.w
                        + f2.x*wb1.x + f2.y*wb1.y + f3.x*wb1.z + f3.y*wb1.w;
                    a2 += f0.x*wc0.x + f0.y*wc0.y + f1.x*wc0.z + f1.y*wc0.w
                        + f2.x*wc1.x + f2.y*wc1.y + f3.x*wc1.z + f3.y*wc1.w;
                }
                a0 += __shfl_xor_sync(0xFFFFFFFFu, a0, 1);
                a1 += __shfl_xor_sync(0xFFFFFFFFu, a1, 1);
                a2 += __shfl_xor_sync(0xFFFFFFFFu, a2, 1);
                a0 += __shfl_xor_sync(0xFFFFFFFFu, a0, 2);
                a1 += __shfl_xor_sync(0xFFFFFFFFu, a1, 2);
                a2 += __shfl_xor_sync(0xFFFFFFFFu, a2, 2);
                if (!sel) {
                    a0 = 1.0f / (1.0f + expf(-(a0 + __ldg(brgb + 0))));
                    a1 = 1.0f / (1.0f + expf(-(a1 + __ldg(brgb + 1))));
                    a2 = 1.0f / (1.0f + expf(-(a2 + __ldg(brgb + 2))));
                    float* orow = out + ((size_t)tile * MTILE + r) * 3;
                    orow[0] = a0; orow[1] = a1; orow[2] = a2;
                }
            }
        }
    }
}

// ----------------------------------------------------------------------------
extern "C" void kernel_launch(void* const* d_in, const int* in_sizes, int n_in,
                              void* d_out, int out_size) {
    Params P;
    for (int i = 0; i < 32; i++) P.p[i] = (const float*)d_in[i];

    const int B = in_sizes[0] / 63;     // x is [B, 63]
    const int ntiles = B / MTILE;       // 64-row tiles

    // prepass: weights -> fp16 padded row-major layout
    wconv_kernel<<<(WH_TOTAL + 255) / 256, 256>>>(P);

    cudaFuncSetAttribute(nerf_fused_fp16,
                         cudaFuncAttributeMaxDynamicSharedMemorySize, SMEM_TOTAL);

    int nsm = 148;
    cudaDeviceGetAttribute(&nsm, cudaDevAttrMultiProcessorCount, 0);
    int grid = (2 * nsm < ntiles) ? 2 * nsm : ntiles;

    nerf_fused_fp16<<<grid, NTHREADS, SMEM_TOTAL>>>(P, (float*)d_out, ntiles, B);
}

// round 14
// speedup vs baseline: 1.0188x; 1.0188x over previous
#include <cuda_runtime.h>
#include <cuda_fp16.h>
#include <cstdint>
#include <math.h>

// ============================================================================
// Fused NeRF MLP (RadianceField), base sm_100 target (no tcgen05).
// fp16 mma.sync.m16n8k16 (fp32 accum) + ldmatrix.x4, persistent 256-thread
// CTAs (1/SM), 128-row tiles. Weights fp16-preconverted, streamed in 64-k
// chunks through a 4-slot cp.async ring gated by mbarriers (producer/consumer,
// cp.async.mbarrier.arrive.NOINC) so warps slip chunk-to-chunk without
// CTA-wide convoys; __syncthreads only at layer boundaries.
// ============================================================================

#define NTHREADS 256
#define MTILE    128

// SMEM map (bytes)
#define ACT_OFF  0                     // 128 rows x 512B (256 half cols), swizzled
#define XB_OFF   65536                 // 128 rows x 128B (64 half cols), swizzled
#define WB_OFF   81920                 // 4 x 32768 weight chunk ring
#define WB_BYTES 32768                 // slot: 256 rows x 128B
#define MB_OFF   (WB_OFF + 4 * WB_BYTES)     // 212992: 4x(full,empty) pairs
#define SMEM_TOTAL (MB_OFF + 256)      // 213248 <= 232448 cap

#define NCHUNKS  45
#define WH_TOTAL 647168

struct Params { const float* p[32]; };

__constant__ int c_widx[13] = {2, 4, 6, 8, 10, 12, 14, 16, 20, 22, 24, 26, 28};
__constant__ int c_kact[13] = {63, 256, 256, 256, 256, 319, 256, 256, 256, 283, 128, 128, 128};
__constant__ int c_kpad[13] = {64, 256, 256, 256, 256, 320, 256, 256, 256, 320, 128, 128, 128};
__constant__ int c_nch [13] = { 1,   4,   4,   4,   4,   5,   4,   4,   4,   5,   2,   2,   2};
__constant__ int c_woff[13] = {0, 16384, 81920, 147456, 212992, 278528, 360448,
                               425984, 491520, 557056, 598016, 614400, 630784};
// flat chunk tables (45 chunks of 64 k-cols)
__constant__ int ck_li[NCHUNKS] = {0,
    1,1,1,1, 2,2,2,2, 3,3,3,3, 4,4,4,4,
    5,5,5,5,5, 6,6,6,6, 7,7,7,7, 8,8,8,8,
    9,9,9,9,9, 10,10, 11,11, 12,12};
__constant__ int ck_c [NCHUNKS] = {0,
    0,1,2,3, 0,1,2,3, 0,1,2,3, 0,1,2,3,
    0,1,2,3,4, 0,1,2,3, 0,1,2,3, 0,1,2,3,
    0,1,2,3,4, 0,1, 0,1, 0,1};

// fp16 weights, per-layer row-major [n][Kpad] (zero-padded)
__device__ __align__(16) __half g_wh[WH_TOTAL];

// ----------------------------------------------------------------------------
__device__ __forceinline__ uint32_t smem_u32_of(const void* p) {
    uint32_t a;
    asm("{ .reg .u64 t; cvta.to.shared.u64 t, %1; cvt.u32.u64 %0, t; }" : "=r"(a) : "l"(p));
    return a;
}
__device__ __forceinline__ void cp_async16(uint32_t dst, const void* src) {
    asm volatile("cp.async.cg.shared.global [%0], [%1], 16;" :: "r"(dst), "l"(src));
}
// NOINC: completion-arrive decrements the init count (init = NTHREADS).
// The default (inc) form self-balances and would deadlock a fixed-count barrier.
__device__ __forceinline__ void cp_async_mbar_arrive_noinc(uint32_t mbar) {
    asm volatile("cp.async.mbarrier.arrive.noinc.shared::cta.b64 [%0];"
                 :: "r"(mbar) : "memory");
}
__device__ __forceinline__ void mbar_init(uint32_t mbar, uint32_t cnt) {
    asm volatile("mbarrier.init.shared.b64 [%0], %1;" :: "r"(mbar), "r"(cnt) : "memory");
}
__device__ __forceinline__ void mbar_arrive(uint32_t mbar) {
    asm volatile("mbarrier.arrive.shared.b64 _, [%0];" :: "r"(mbar) : "memory");
}
__device__ __forceinline__ void mbar_wait(uint32_t mbar, uint32_t parity) {
    uint32_t done;
    asm volatile(
        "{\n\t.reg .pred p;\n\t"
        "mbarrier.try_wait.parity.acquire.cta.shared::cta.b64 p, [%1], %2;\n\t"
        "selp.b32 %0, 1, 0, p;\n\t}"
        : "=r"(done) : "r"(mbar), "r"(parity) : "memory");
    if (!done) {
        asm volatile(
            "{\n\t.reg .pred P1;\n\t"
            "WAIT_LOOP_%=:\n\t"
            "mbarrier.try_wait.parity.acquire.cta.shared::cta.b64 P1, [%0], %1, 0x989680;\n\t"
            "@P1 bra.uni WAIT_DONE_%=;\n\t"
            "bra.uni WAIT_LOOP_%=;\n\t"
            "WAIT_DONE_%=:\n\t}"
            :: "r"(mbar), "r"(parity) : "memory");
    }
}
__device__ __forceinline__ void ldsm_x4(uint32_t r[4], uint32_t addr) {
    asm volatile("ldmatrix.sync.aligned.m8n8.x4.shared.b16 {%0,%1,%2,%3}, [%4];"
                 : "=r"(r[0]), "=r"(r[1]), "=r"(r[2]), "=r"(r[3]) : "r"(addr));
}
__device__ __forceinline__ void mma_f16(float c[4], uint32_t a0, uint32_t a1,
                                        uint32_t a2, uint32_t a3,
                                        uint32_t b0, uint32_t b1) {
    asm volatile(
        "mma.sync.aligned.m16n8k16.row.col.f32.f16.f16.f32 "
        "{%0,%1,%2,%3}, {%4,%5,%6,%7}, {%8,%9}, {%0,%1,%2,%3};"
        : "+f"(c[0]), "+f"(c[1]), "+f"(c[2]), "+f"(c[3])
        : "r"(a0), "r"(a1), "r"(a2), "r"(a3), "r"(b0), "r"(b1));
}
__device__ __forceinline__ void sts32(uint32_t addr, uint32_t v) {
    asm volatile("st.shared.b32 [%0], %1;" :: "r"(addr), "r"(v));
}
__device__ __forceinline__ void sts128(uint32_t addr, uint32_t a, uint32_t b,
                                       uint32_t c, uint32_t d) {
    asm volatile("st.shared.v4.b32 [%0], {%1,%2,%3,%4};"
                 :: "r"(addr), "r"(a), "r"(b), "r"(c), "r"(d));
}
__device__ __forceinline__ uint4 lds128(uint32_t addr) {
    uint4 u;
    asm volatile("ld.shared.v4.b32 {%0,%1,%2,%3}, [%4];"
                 : "=r"(u.x), "=r"(u.y), "=r"(u.z), "=r"(u.w) : "r"(addr));
    return u;
}
__device__ __forceinline__ uint32_t h2u(__half2 h) { return *(uint32_t*)&h; }

// ============================================================================
// Prepass: fp32 weights -> fp16, zero-padded, per-layer [n][Kpad] row-major
// ============================================================================
__global__ void wconv_kernel(Params P) {
    int i = blockIdx.x * blockDim.x + threadIdx.x;
    if (i >= WH_TOTAL) return;
    int li = 0;
#pragma unroll
    for (int l = 1; l < 13; l++) if (i >= c_woff[l]) li = l;
    int e = i - c_woff[li];
    int Kp = c_kpad[li];
    int n = e / Kp;
    int k = e - n * Kp;
    int Kact = c_kact[li];
    float v = (k < Kact) ? __ldg(P.p[c_widx[li]] + (size_t)n * Kact + k) : 0.0f;
    g_wh[i] = __float2half_rn(v);
}

// ============================================================================
// Issue one 64-k chunk (table idx j45) into ring slot; noinc-arrive on the
// slot's full barrier when this thread's copies land (256 arrivals -> flip).
// Slot layout: row n = 128B (8 granules), XOR-swizzled by (n&7).
// ============================================================================
__device__ __forceinline__ void issue_chunk(int j45, uint32_t slot, uint32_t full_mbar,
                                            int tid) {
    const int li = ck_li[j45], c = ck_c[j45];
    const int N = (li < 9) ? 256 : 128;
    const int Kp = c_kpad[li];
    const __half* __restrict__ base = g_wh + c_woff[li] + c * 64;
    const int tot = N * 8;   // granules
#pragma unroll 4
    for (int f = tid; f < tot; f += NTHREADS) {
        int n = f >> 3, g = f & 7;
        cp_async16(slot + (uint32_t)(n * 128 + ((g ^ (n & 7)) << 4)),
                   base + (size_t)n * Kp + g * 8);
    }
    cp_async_mbar_arrive_noinc(full_mbar);
}

// ============================================================================
// Compute one 64-k chunk (4 k-steps). Warp (wm, wn): rows [wm*64,+64),
// cols [wn*NT*8, +NT*8). XBSRC: A from XB (128B rows), else ACT (512B rows).
// ============================================================================
template <int NT, bool XBSRC>
__device__ __forceinline__ void compute_chunk(float acc[4][8][4], uint32_t abase, int cb,
                                              uint32_t wb, int lane, int wm, int wn) {
    const int arow = lane & 15;
    const int asel = lane >> 4;
    const int brow = lane & 7;
    const int bsel = (lane >> 3) & 1;
    const int bnto = lane >> 4;
    const int RS = XBSRC ? 128 : 512;
    const uint32_t a_base = abase + (uint32_t)((wm * 64 + arow) * RS);
    const int sA = arow & 7;
    const int cbb = (cb >> 3) + asel;
#pragma unroll
    for (int ks = 0; ks < 4; ks++) {
        uint32_t b0[NT], b1[NT];
#pragma unroll
        for (int p = 0; p < NT / 2; p++) {
            int n = wn * (NT * 8) + (2 * p + bnto) * 8 + brow;
            int gr = ks * 2 + bsel;
            uint32_t q[4];
            ldsm_x4(q, wb + (uint32_t)(n * 128 + ((gr ^ (n & 7)) << 4)));
            b0[2 * p] = q[0]; b1[2 * p] = q[1];
            b0[2 * p + 1] = q[2]; b1[2 * p + 1] = q[3];
        }
#pragma unroll
        for (int mt = 0; mt < 4; mt++) {
            uint32_t a[4];
            int gr = cbb + ks * 2;
            ldsm_x4(a, a_base + (uint32_t)(mt * 16 * RS + ((gr ^ sA) << 4)));
#pragma unroll
            for (int nt = 0; nt < NT; nt++)
                mma_f16(acc[mt][nt], a[0], a[1], a[2], a[3], b0[nt], b1[nt]);
        }
    }
}

template <int NT>
__device__ __forceinline__ void zero_acc(float acc[4][8][4]) {
#pragma unroll
    for (int m = 0; m < 4; m++)
#pragma unroll
        for (int n = 0; n < NT; n++)
#pragma unroll
            for (int q = 0; q < 4; q++) acc[m][n][q] = 0.0f;
}

template <int NT>
__device__ __forceinline__ void epilogue(float acc[4][8][4], uint32_t act_u,
                                         const float* __restrict__ bb, bool relu,
                                         int lane, int wm, int wn) {
#pragma unroll
    for (int mt = 0; mt < 4; mt++) {
        int row0 = wm * 64 + mt * 16 + (lane >> 2);
        int row1 = row0 + 8;
#pragma unroll
        for (int nt = 0; nt < NT; nt++) {
            int col0 = wn * (NT * 8) + nt * 8 + 2 * (lane & 3);
            float2 bv = __ldg((const float2*)(bb + col0));
            float v0 = acc[mt][nt][0] + bv.x;
            float v1 = acc[mt][nt][1] + bv.y;
            float v2 = acc[mt][nt][2] + bv.x;
            float v3 = acc[mt][nt][3] + bv.y;
            if (relu) {
                v0 = fmaxf(v0, 0.0f); v1 = fmaxf(v1, 0.0f);
                v2 = fmaxf(v2, 0.0f); v3 = fmaxf(v3, 0.0f);
            }
            int g = col0 >> 3, cb2 = (col0 & 7) * 2;
            sts32(act_u + (uint32_t)(row0 * 512 + ((g ^ (row0 & 7)) << 4) + cb2),
                  h2u(__floats2half2_rn(v0, v1)));
            sts32(act_u + (uint32_t)(row1 * 512 + ((g ^ (row1 & 7)) << 4) + cb2),
                  h2u(__floats2half2_rn(v2, v3)));
        }
    }
}

// ============================================================================
// Kernel
// ============================================================================
__global__ void __launch_bounds__(NTHREADS, 1)
nerf_fused_fp16(Params P, float* __restrict__ out, int ntiles, int Btot) {
    extern __shared__ __align__(1024) char sm[];
    const uint32_t sb = smem_u32_of(sm);
    const uint32_t act_u = sb + ACT_OFF;
    const uint32_t xb_u  = sb + XB_OFF;
    const uint32_t wb_u  = sb + WB_OFF;
    const uint32_t mb_u  = sb + MB_OFF;   // full[s]=mb_u+s*16, empty[s]=+8

    const int tid = threadIdx.x;
    const int lane = tid & 31;
    const int w = tid >> 5;
    const int wm = w >> 2;     // 0..1 (64-row half)
    const int wn = w & 3;      // 0..3 (col slice)

    const float* __restrict__ xin  = P.p[0];
    const float* __restrict__ ddir = P.p[1];
    const float* __restrict__ wsig = P.p[18];
    const float  bsig = __ldg(P.p[19]);
    const float* __restrict__ wrgb = P.p[30];
    const float* __restrict__ brgb = P.p[31];

    float acc[4][8][4];

    // ---- init mbarriers (full & empty: 256 arrivals each)
    if (tid < 4) {
        mbar_init(mb_u + tid * 16, NTHREADS);
        mbar_init(mb_u + tid * 16 + 8, NTHREADS);
    }
    __syncthreads();

    // ---- prime ring: issue chunks 0..2 (no empty wait: first use of slots)
    uint32_t Gc = 0;           // global compute-chunk counter
    int jn = 3;                // table index of next chunk to issue
    {
        issue_chunk(0, wb_u + 0 * WB_BYTES, mb_u + 0 * 16, tid);
        issue_chunk(1, wb_u + 1 * WB_BYTES, mb_u + 1 * 16, tid);
        issue_chunk(2, wb_u + 2 * WB_BYTES, mb_u + 2 * 16, tid);
    }

    for (int tile = blockIdx.x; tile < ntiles; tile += gridDim.x) {
        // ---- x -> XB (fp16, swizzled 128B rows); cols 0..62 = x, col 63 = 0
        {
            int r = tid >> 1, sel = tid & 1;
            const float* xr = xin + ((size_t)tile * MTILE + r) * 63;
#pragma unroll
            for (int gi = 0; gi < 4; gi++) {
                int g = sel * 4 + gi;
                int c0 = g * 8;
                uint32_t u[4];
#pragma unroll
                for (int q = 0; q < 4; q++) {
                    int c = c0 + q * 2;
                    float f0 = (c < 63) ? __ldg(xr + c) : 0.0f;
                    float f1 = (c + 1 < 63) ? __ldg(xr + c + 1) : 0.0f;
                    u[q] = h2u(__floats2half2_rn(f0, f1));
                }
                sts128(xb_u + (uint32_t)(r * 128 + ((g ^ (r & 7)) << 4)),
                       u[0], u[1], u[2], u[3]);
            }
        }
        __syncthreads();   // XB staged (and prev tile fully done)

        for (int li = 0; li < 13; li++) {
            const int nch = c_nch[li];
            const bool n256 = (li < 9);
            const float* __restrict__ bb = P.p[c_widx[li] + 1];

            if (n256) zero_acc<8>(acc); else zero_acc<4>(acc);

            for (int c = 0; c < nch; c++) {
                // ---- producer: issue chunk Gc+3 into its slot
                {
                    uint32_t j = Gc + 3;
                    uint32_t s = j & 3;
                    if (j >= 4) {
                        // slot reuse: wait consumers of chunk j-4 (= Gc-1)
                        uint32_t ep = (((j >> 2) + 1) & 1);
                        mbar_wait(mb_u + s * 16 + 8, ep);
                    }
                    issue_chunk(jn, wb_u + s * WB_BYTES, mb_u + s * 16, tid);
                    jn = (jn + 1 == NCHUNKS) ? 0 : jn + 1;
                }
                // ---- consumer: wait chunk Gc full, compute, release slot
                {
                    uint32_t s = Gc & 3;
                    mbar_wait(mb_u + s * 16, (Gc >> 2) & 1);
                    const uint32_t wb = wb_u + s * WB_BYTES;
                    bool xbs = (li == 0) || ((li == 5 || li == 9) && c == 4);
                    if (n256) {
                        if (xbs) compute_chunk<8, true >(acc, xb_u, 0, wb, lane, wm, wn);
                        else     compute_chunk<8, false>(acc, act_u, c * 64, wb, lane, wm, wn);
                    } else {
                        if (xbs) compute_chunk<4, true >(acc, xb_u, 0, wb, lane, wm, wn);
                        else     compute_chunk<4, false>(acc, act_u, c * 64, wb, lane, wm, wn);
                    }
                    mbar_arrive(mb_u + s * 16 + 8);
                }
                Gc++;
            }

            __syncthreads();   // all warps' reads of ACT/XB for this layer done
            if (n256) epilogue<8>(acc, act_u, bb, li != 8, lane, wm, wn);
            else      epilogue<4>(acc, act_u, bb, li != 8, lane, wm, wn);

            if (li == 5) {
                // d -> XB (x is dead): cols 0..26 = d, rest 0
                int r = tid >> 1, sel = tid & 1;
                const float* dr = ddir + ((size_t)tile * MTILE + r) * 27;
#pragma unroll
                for (int gi = 0; gi < 4; gi++) {
                    int g = sel * 4 + gi;
                    int c0 = g * 8;
                    uint32_t u[4];
#pragma unroll
                    for (int q = 0; q < 4; q++) {
                        int c = c0 + q * 2;
                        float f0 = (c < 27) ? __ldg(dr + c) : 0.0f;
                        float f1 = (c + 1 < 27) ? __ldg(dr + c + 1) : 0.0f;
                        u[q] = h2u(__floats2half2_rn(f0, f1));
                    }
                    sts128(xb_u + (uint32_t)(r * 128 + ((g ^ (r & 7)) << 4)),
                           u[0], u[1], u[2], u[3]);
                }
            }
            __syncthreads();   // epilogue (and d) visible to next layer

            if (li == 7) {
                // sigma = softplus(h7 . wsig + bsig); 2 threads/row (reads only)
                int r = tid >> 1, sel = tid & 1;
                float a = 0.0f;
#pragma unroll
                for (int i = 0; i < 16; i++) {
                    int g = sel * 16 + i;
                    uint4 u = lds128(act_u + (uint32_t)(r * 512 + ((g ^ (r & 7)) << 4)));
                    __half2* hp = (__half2*)&u;
                    float4 w0 = __ldg((const float4*)(wsig + g * 8));
                    float4 w1 = __ldg((const float4*)(wsig + g * 8 + 4));
                    float2 f;
                    f = __half22float2(hp[0]); a += f.x * w0.x + f.y * w0.y;
                    f = __half22float2(hp[1]); a += f.x * w0.z + f.y * w0.w;
                    f = __half22float2(hp[2]); a += f.x * w1.x + f.y * w1.y;
                    f = __half22float2(hp[3]); a += f.x * w1.z + f.y * w1.w;
                }
                a += __shfl_xor_sync(0xFFFFFFFFu, a, 1);
                if (!sel) {
                    float z = a + bsig;
                    float sp = fmaxf(z, 0.0f) + log1pf(expf(-fabsf(z)));
                    out[(size_t)3 * Btot + (size_t)tile * MTILE + r] = sp;
                }
            }
            if (li == 12 && tid < MTILE) {
                // rgb = sigmoid(h12 @ Wrgb^T + brgb)
                int r = tid;
                float a0 = 0.0f, a1 = 0.0f, a2 = 0.0f;
#pragma unroll
                for (int i = 0; i < 16; i++) {
                    uint4 u = lds128(act_u + (uint32_t)(r * 512 + ((i ^ (r & 7)) << 4)));
                    __half2* hp = (__half2*)&u;
                    float4 wa0 = __ldg((const float4*)(wrgb + i * 8));
                    float4 wa1 = __ldg((const float4*)(wrgb + i * 8 + 4));
                    float4 wb0 = __ldg((const float4*)(wrgb + 128 + i * 8));
                    float4 wb1 = __ldg((const float4*)(wrgb + 128 + i * 8 + 4));
                    float4 wc0 = __ldg((const float4*)(wrgb + 256 + i * 8));
                    float4 wc1 = __ldg((const float4*)(wrgb + 256 + i * 8 + 4));
                    float2 f0 = __half22float2(hp[0]);
                    float2 f1 = __half22float2(hp[1]);
                    float2 f2 = __half22float2(hp[2]);
                    float2 f3 = __half22float2(hp[3]);
                    a0 += f0.x*wa0.x + f0.y*wa0.y + f1.x*wa0.z + f1.y*wa0.w
                        + f2.x*wa1.x + f2.y*wa1.y + f3.x*wa1.z + f3.y*wa1.w;
                    a1 += f0.x*wb0.x + f0.y*wb0.y + f1.x*wb0.z + f1.y*wb0.w
                        + f2.x*wb1.x + f2.y*wb1.y + f3.x*wb1.z + f3.y*wb1.w;
                    a2 += f0.x*wc0.x + f0.y*wc0.y + f1.x*wc0.z + f1.y*wc0.w
                        + f2.x*wc1.x + f2.y*wc1.y + f3.x*wc1.z + f3.y*wc1.w;
                }
                a0 = 1.0f / (1.0f + expf(-(a0 + __ldg(brgb + 0))));
                a1 = 1.0f / (1.0f + expf(-(a1 + __ldg(brgb + 1))));
                a2 = 1.0f / (1.0f + expf(-(a2 + __ldg(brgb + 2))));
                float* orow = out + ((size_t)tile * MTILE + r) * 3;
                orow[0] = a0; orow[1] = a1; orow[2] = a2;
            }
        }
    }
}

// ----------------------------------------------------------------------------
extern "C" void kernel_launch(void* const* d_in, const int* in_sizes, int n_in,
                              void* d_out, int out_size) {
    Params P;
    for (int i = 0; i < 32; i++) P.p[i] = (const float*)d_in[i];

    const int B = in_sizes[0] / 63;     // x is [B, 63]
    const int ntiles = B / MTILE;

    // prepass: weights -> fp16 padded row-major layout
    wconv_kernel<<<(WH_TOTAL + 255) / 256, 256>>>(P);

    cudaFuncSetAttribute(nerf_fused_fp16,
                         cudaFuncAttributeMaxDynamicSharedMemorySize, SMEM_TOTAL);

    int nsm = 148;
    cudaDeviceGetAttribute(&nsm, cudaDevAttrMultiProcessorCount, 0);
    int grid = (nsm < ntiles) ? nsm : ntiles;

    nerf_fused_fp16<<<grid, NTHREADS, SMEM_TOTAL>>>(P, (float*)d_out, ntiles, B);
}

// round 15
// speedup vs baseline: 1.1286x; 1.1078x over previous
#include <cuda_runtime.h>
#include <cuda_fp16.h>
#include <cstdint>
#include <math.h>

// ============================================================================
// Fused NeRF MLP (RadianceField), base sm_100 target (no tcgen05).
// fp16 mma.sync.m16n8k16 (fp32 accum) + ldmatrix.x4, persistent 256-thread
// CTAs, weights pre-converted to fp16 and streamed in 128-k chunks through a
// 2-slot cp.async ring (lookahead 1), fp16 activations in SMEM.
// R15: minimal barriers (chunk-0 sync of next layer subsumes post-epilogue
// syncs), relu via __hmax2 after cvt.
// ============================================================================

#define NTHREADS 256
#define MTILE    128

// SMEM map (bytes)
#define ACT_OFF  0                     // 128 rows x 512B (256 half cols), swizzled
#define XB_OFF   65536                 // 128 rows x 256B (128 half cols), swizzled
#define WB_OFF   98304                 // 2 x 65536 weight chunk ring
#define WB_BYTES 65536                 // slot: 256 rows x 256B
#define SMEM_TOTAL (WB_OFF + 2 * WB_BYTES)   // 229376 <= 232448 cap

#define NCHUNKS  24
#define WH_TOTAL 647168

struct Params { const float* p[32]; };

__constant__ int c_widx[13] = {2, 4, 6, 8, 10, 12, 14, 16, 20, 22, 24, 26, 28};
__constant__ int c_kact[13] = {63, 256, 256, 256, 256, 319, 256, 256, 256, 283, 128, 128, 128};
__constant__ int c_kpad[13] = {64, 256, 256, 256, 256, 320, 256, 256, 256, 320, 128, 128, 128};
__constant__ int c_nch [13] = { 1,   2,   2,   2,   2,   3,   2,   2,   2,   3,   1,   1,   1};
__constant__ int c_woff[13] = {0, 16384, 81920, 147456, 212992, 278528, 360448,
                               425984, 491520, 557056, 598016, 614400, 630784};
// flat chunk tables
__constant__ int ck_li[NCHUNKS] = {0, 1,1, 2,2, 3,3, 4,4, 5,5,5, 6,6, 7,7, 8,8, 9,9,9, 10, 11, 12};
__constant__ int ck_c [NCHUNKS] = {0, 0,1, 0,1, 0,1, 0,1, 0,1,2, 0,1, 0,1, 0,1, 0,1,2, 0, 0, 0};

// fp16 weights, per-layer row-major [n][Kpad] (zero-padded)
__device__ __align__(16) __half g_wh[WH_TOTAL];

// ----------------------------------------------------------------------------
__device__ __forceinline__ uint32_t smem_u32_of(const void* p) {
    uint32_t a;
    asm("{ .reg .u64 t; cvta.to.shared.u64 t, %1; cvt.u32.u64 %0, t; }" : "=r"(a) : "l"(p));
    return a;
}
__device__ __forceinline__ void cp_async16(uint32_t dst, const void* src) {
    asm volatile("cp.async.cg.shared.global [%0], [%1], 16;" :: "r"(dst), "l"(src));
}
__device__ __forceinline__ void cp_commit() { asm volatile("cp.async.commit_group;"); }
template <int N> __device__ __forceinline__ void cp_wait() {
    asm volatile("cp.async.wait_group %0;" :: "n"(N));
}
__device__ __forceinline__ void ldsm_x4(uint32_t r[4], uint32_t addr) {
    asm volatile("ldmatrix.sync.aligned.m8n8.x4.shared.b16 {%0,%1,%2,%3}, [%4];"
                 : "=r"(r[0]), "=r"(r[1]), "=r"(r[2]), "=r"(r[3]) : "r"(addr));
}
__device__ __forceinline__ void mma_f16(float c[4], uint32_t a0, uint32_t a1,
                                        uint32_t a2, uint32_t a3,
                                        uint32_t b0, uint32_t b1) {
    asm volatile(
        "mma.sync.aligned.m16n8k16.row.col.f32.f16.f16.f32 "
        "{%0,%1,%2,%3}, {%4,%5,%6,%7}, {%8,%9}, {%0,%1,%2,%3};"
        : "+f"(c[0]), "+f"(c[1]), "+f"(c[2]), "+f"(c[3])
        : "r"(a0), "r"(a1), "r"(a2), "r"(a3), "r"(b0), "r"(b1));
}
__device__ __forceinline__ void sts32(uint32_t addr, uint32_t v) {
    asm volatile("st.shared.b32 [%0], %1;" :: "r"(addr), "r"(v));
}
__device__ __forceinline__ void sts128(uint32_t addr, uint32_t a, uint32_t b,
                                       uint32_t c, uint32_t d) {
    asm volatile("st.shared.v4.b32 [%0], {%1,%2,%3,%4};"
                 :: "r"(addr), "r"(a), "r"(b), "r"(c), "r"(d));
}
__device__ __forceinline__ uint4 lds128(uint32_t addr) {
    uint4 u;
    asm volatile("ld.shared.v4.b32 {%0,%1,%2,%3}, [%4];"
                 : "=r"(u.x), "=r"(u.y), "=r"(u.z), "=r"(u.w) : "r"(addr));
    return u;
}
__device__ __forceinline__ uint32_t h2u(__half2 h) { return *(uint32_t*)&h; }

// ============================================================================
// Prepass: fp32 weights -> fp16, zero-padded, per-layer [n][Kpad] row-major
// ============================================================================
__global__ void wconv_kernel(Params P) {
    int i = blockIdx.x * blockDim.x + threadIdx.x;
    if (i >= WH_TOTAL) return;
    int li = 0;
#pragma unroll
    for (int l = 1; l < 13; l++) if (i >= c_woff[l]) li = l;
    int e = i - c_woff[li];
    int Kp = c_kpad[li];
    int n = e / Kp;
    int k = e - n * Kp;
    int Kact = c_kact[li];
    float v = (k < Kact) ? __ldg(P.p[c_widx[li]] + (size_t)n * Kact + k) : 0.0f;
    g_wh[i] = __float2half_rn(v);
}

// ============================================================================
// Weight chunk issue: slice of layer li into ring slot.
// Slot layout: row n = 256B, 16B granules XOR-swizzled by (n&7).
// ============================================================================
__device__ __forceinline__ void issue_chunk(int idx, uint32_t slot, int tid) {
    const int li = ck_li[idx], c = ck_c[idx];
    const int N = (li < 9) ? 256 : 128;
    const int Kp = c_kpad[li];
    const int KS = (li == 0 || ((li == 5 || li == 9) && c == 2)) ? 4 : 8;
    const int ks2 = 2 * KS;                 // granules per row
    const __half* __restrict__ base = g_wh + c_woff[li] + c * 128;
    const int tot = N * ks2;
    const int sh = (KS == 8) ? 4 : 3;
    const int msk = ks2 - 1;
    for (int f = tid; f < tot; f += NTHREADS) {
        int n = f >> sh, g = f & msk;
        cp_async16(slot + (uint32_t)(n * 256 + ((g ^ (n & 7)) << 4)),
                   base + (size_t)n * Kp + g * 8);
    }
    cp_commit();
}

// ============================================================================
// Compute one chunk: KS k-steps of 16. Warp (wm, wn): rows [wm*64,+64),
// cols [wn*NT*8, +NT*8). XBSRC: A from XB (256B rows), else ACT (512B rows).
// ============================================================================
template <int NT, int KS, bool XBSRC>
__device__ __forceinline__ void compute_chunk(float acc[4][8][4], uint32_t abase, int cb,
                                              uint32_t wb, int lane, int wm, int wn) {
    const int arow = lane & 15;
    const int asel = lane >> 4;
    const int brow = lane & 7;
    const int bsel = (lane >> 3) & 1;
    const int bnto = lane >> 4;
    const int RS = XBSRC ? 256 : 512;
    const uint32_t a_base = abase + (uint32_t)((wm * 64 + arow) * RS);
    const int sA = arow & 7;
    const int cbb = (cb >> 3) + asel;
#pragma unroll
    for (int ks = 0; ks < KS; ks++) {
        uint32_t b0[NT], b1[NT];
#pragma unroll
        for (int p = 0; p < NT / 2; p++) {
            int n = wn * (NT * 8) + (2 * p + bnto) * 8 + brow;
            int gr = ks * 2 + bsel;
            uint32_t q[4];
            ldsm_x4(q, wb + (uint32_t)(n * 256 + ((gr ^ brow) << 4)));
            b0[2 * p] = q[0]; b1[2 * p] = q[1];
            b0[2 * p + 1] = q[2]; b1[2 * p + 1] = q[3];
        }
#pragma unroll
        for (int mt = 0; mt < 4; mt++) {
            uint32_t a[4];
            int gr = cbb + ks * 2;
            ldsm_x4(a, a_base + (uint32_t)(mt * 16 * RS + ((gr ^ sA) << 4)));
#pragma unroll
            for (int nt = 0; nt < NT; nt++)
                mma_f16(acc[mt][nt], a[0], a[1], a[2], a[3], b0[nt], b1[nt]);
        }
    }
}

template <int NT>
__device__ __forceinline__ void zero_acc(float acc[4][8][4]) {
#pragma unroll
    for (int m = 0; m < 4; m++)
#pragma unroll
        for (int n = 0; n < NT; n++)
#pragma unroll
            for (int q = 0; q < 4; q++) acc[m][n][q] = 0.0f;
}

// Epilogue: bias (fp32) + cvt to half2 + (relu via hmax2), write to ACT.
template <int NT>
__device__ __forceinline__ void epilogue(float acc[4][8][4], uint32_t act_u,
                                         const float* __restrict__ bb, bool relu,
                                         int lane, int wm, int wn) {
    const __half2 z2 = __floats2half2_rn(0.0f, 0.0f);
#pragma unroll
    for (int mt = 0; mt < 4; mt++) {
        int row0 = wm * 64 + mt * 16 + (lane >> 2);
        int row1 = row0 + 8;
#pragma unroll
        for (int nt = 0; nt < NT; nt++) {
            int col0 = wn * (NT * 8) + nt * 8 + 2 * (lane & 3);
            float2 bv = __ldg((const float2*)(bb + col0));
            __half2 h0 = __floats2half2_rn(acc[mt][nt][0] + bv.x,
                                           acc[mt][nt][1] + bv.y);
            __half2 h1 = __floats2half2_rn(acc[mt][nt][2] + bv.x,
                                           acc[mt][nt][3] + bv.y);
            if (relu) { h0 = __hmax2(h0, z2); h1 = __hmax2(h1, z2); }
            int g = col0 >> 3, cb2 = (col0 & 7) * 2;
            sts32(act_u + (uint32_t)(row0 * 512 + ((g ^ (row0 & 7)) << 4) + cb2), h2u(h0));
            sts32(act_u + (uint32_t)(row1 * 512 + ((g ^ (row1 & 7)) << 4) + cb2), h2u(h1));
        }
    }
}

// ============================================================================
// Kernel
// ============================================================================
__global__ void __launch_bounds__(NTHREADS, 1)
nerf_fused_fp16(Params P, float* __restrict__ out, int ntiles, int Btot) {
    extern __shared__ __align__(1024) char sm[];
    const uint32_t sb = smem_u32_of(sm);
    const uint32_t act_u = sb + ACT_OFF;
    const uint32_t xb_u  = sb + XB_OFF;
    const uint32_t wb_u  = sb + WB_OFF;

    const int tid = threadIdx.x;
    const int lane = tid & 31;
    const int w = tid >> 5;
    const int wm = w >> 2;
    const int wn = w & 3;

    const float* __restrict__ xin  = P.p[0];
    const float* __restrict__ ddir = P.p[1];
    const float* __restrict__ wsig = P.p[18];
    const float  bsig = __ldg(P.p[19]);
    const float* __restrict__ wrgb = P.p[30];
    const float* __restrict__ brgb = P.p[31];

    float acc[4][8][4];

    for (int tile = blockIdx.x; tile < ntiles; tile += gridDim.x) {
        // ---- prologue: issue chunk 0 into slot 0
        issue_chunk(0, wb_u, tid);

        // ---- x -> XB (fp16, swizzled); cols 0..62 = x, 63..127 = 0
        // (chunk-0 barrier below orders these writes before any reads; previous
        //  tile's XB readers finished before its own layer-9 chunk barriers)
        {
            int r = tid >> 1, sel = tid & 1;
            const float* xr = xin + ((size_t)tile * MTILE + r) * 63;
#pragma unroll
            for (int gi = 0; gi < 8; gi++) {
                int g = sel * 8 + gi;
                int c0 = g * 8;
                uint32_t u[4];
#pragma unroll
                for (int q = 0; q < 4; q++) {
                    int c = c0 + q * 2;
                    float f0 = (c < 63) ? __ldg(xr + c) : 0.0f;
                    float f1 = (c + 1 < 63) ? __ldg(xr + c + 1) : 0.0f;
                    u[q] = h2u(__floats2half2_rn(f0, f1));
                }
                sts128(xb_u + (uint32_t)(r * 256 + ((g ^ (r & 7)) << 4)),
                       u[0], u[1], u[2], u[3]);
            }
        }

        int gc = 0;
        for (int li = 0; li < 13; li++) {
            const int nch = c_nch[li];
            const bool n256 = (li < 9);
            const float* __restrict__ bb = P.p[c_widx[li] + 1];

            if (n256) zero_acc<8>(acc); else zero_acc<4>(acc);

            for (int c = 0; c < nch; c++) {
                cp_wait<0>();      // this chunk's data arrived (per-thread)
                __syncthreads();   // visible to all; all warps done w/ gc-1;
                                   // also orders prior epilogue/stage writes

                if (gc + 1 < NCHUNKS)
                    issue_chunk(gc + 1, wb_u + ((gc + 1) & 1) * WB_BYTES, tid);

                const uint32_t wb = wb_u + (gc & 1) * WB_BYTES;
                if (li == 0)
                    compute_chunk<8, 4, true >(acc, xb_u, 0, wb, lane, wm, wn);
                else if (li == 5 && c == 2)
                    compute_chunk<8, 4, true >(acc, xb_u, 0, wb, lane, wm, wn);
                else if (li == 9 && c == 2)
                    compute_chunk<4, 4, true >(acc, xb_u, 0, wb, lane, wm, wn);
                else if (n256)
                    compute_chunk<8, 8, false>(acc, act_u, c * 128, wb, lane, wm, wn);
                else
                    compute_chunk<4, 8, false>(acc, act_u, c * 128, wb, lane, wm, wn);
                gc++;
            }

            __syncthreads();   // all warps' reads of ACT/XB this layer done (WAR)
            if (n256) epilogue<8>(acc, act_u, bb, li != 8, lane, wm, wn);
            else      epilogue<4>(acc, act_u, bb, li != 8, lane, wm, wn);
            // NOTE: no post-epilogue barrier — the next layer's chunk-0
            // cp_wait+__syncthreads orders epilogue writes before ACT reads.

            if (li == 5) {
                // d -> XB (x is dead): cols 0..26 = d, rest 0.
                // Safe: pre-epilogue barrier above guarantees all warps
                // finished layer-5 chunk-2 (the XB reads).
                int r = tid >> 1, sel = tid & 1;
                const float* dr = ddir + ((size_t)tile * MTILE + r) * 27;
#pragma unroll
                for (int gi = 0; gi < 8; gi++) {
                    int g = sel * 8 + gi;
                    int c0 = g * 8;
                    uint32_t u[4];
#pragma unroll
                    for (int q = 0; q < 4; q++) {
                        int c = c0 + q * 2;
                        float f0 = (c < 27) ? __ldg(dr + c) : 0.0f;
                        float f1 = (c + 1 < 27) ? __ldg(dr + c + 1) : 0.0f;
                        u[q] = h2u(__floats2half2_rn(f0, f1));
                    }
                    sts128(xb_u + (uint32_t)(r * 256 + ((g ^ (r & 7)) << 4)),
                           u[0], u[1], u[2], u[3]);
                }
            }

            if (li == 7) {
                __syncthreads();   // epilogue visible for head
                // sigma = softplus(h7 . wsig + bsig); 2 threads/row
                int r = tid >> 1, sel = tid & 1;
                float a = 0.0f;
#pragma unroll
                for (int i = 0; i < 16; i++) {
                    int g = sel * 16 + i;
                    uint4 u = lds128(act_u + (uint32_t)(r * 512 + ((g ^ (r & 7)) << 4)));
                    __half2* hp = (__half2*)&u;
                    float4 w0 = __ldg((const float4*)(wsig + sel * 128 + i * 8));
                    float4 w1 = __ldg((const float4*)(wsig + sel * 128 + i * 8 + 4));
                    float2 f;
                    f = __half22float2(hp[0]); a += f.x * w0.x + f.y * w0.y;
                    f = __half22float2(hp[1]); a += f.x * w0.z + f.y * w0.w;
                    f = __half22float2(hp[2]); a += f.x * w1.x + f.y * w1.y;
                    f = __half22float2(hp[3]); a += f.x * w1.z + f.y * w1.w;
                }
                a += __shfl_xor_sync(0xFFFFFFFFu, a, 1);
                if (!sel) {
                    float z = a + bsig;
                    float sp = fmaxf(z, 0.0f) + log1pf(expf(-fabsf(z)));
                    out[(size_t)3 * Btot + (size_t)tile * MTILE + r] = sp;
                }
                // head reads complete before layer-8 epilogue overwrites ACT:
                // layer-8's chunk-0 barrier + pre-epilogue barrier intervene.
            }
            if (li == 12) {
                __syncthreads();   // epilogue visible for head
                if (tid < MTILE) {
                    // rgb = sigmoid(h12 @ Wrgb^T + brgb)
                    int r = tid;
                    float a0 = 0.0f, a1 = 0.0f, a2 = 0.0f;
#pragma unroll
                    for (int i = 0; i < 16; i++) {
                        uint4 u = lds128(act_u + (uint32_t)(r * 512 + ((i ^ (r & 7)) << 4)));
                        __half2* hp = (__half2*)&u;
                        float4 wa0 = __ldg((const float4*)(wrgb + i * 8));
                        float4 wa1 = __ldg((const float4*)(wrgb + i * 8 + 4));
                        float4 wb0 = __ldg((const float4*)(wrgb + 128 + i * 8));
                        float4 wb1 = __ldg((const float4*)(wrgb + 128 + i * 8 + 4));
                        float4 wc0 = __ldg((const float4*)(wrgb + 256 + i * 8));
                        float4 wc1 = __ldg((const float4*)(wrgb + 256 + i * 8 + 4));
                        float2 f0 = __half22float2(hp[0]);
                        float2 f1 = __half22float2(hp[1]);
                        float2 f2 = __half22float2(hp[2]);
                        float2 f3 = __half22float2(hp[3]);
                        a0 += f0.x*wa0.x + f0.y*wa0.y + f1.x*wa0.z + f1.y*wa0.w
                            + f2.x*wa1.x + f2.y*wa1.y + f3.x*wa1.z + f3.y*wa1.w;
                        a1 += f0.x*wb0.x + f0.y*wb0.y + f1.x*wb0.z + f1.y*wb0.w
                            + f2.x*wb1.x + f2.y*wb1.y + f3.x*wb1.z + f3.y*wb1.w;
                        a2 += f0.x*wc0.x + f0.y*wc0.y + f1.x*wc0.z + f1.y*wc0.w
                            + f2.x*wc1.x + f2.y*wc1.y + f3.x*wc1.z + f3.y*wc1.w;
                    }
                    a0 = 1.0f / (1.0f + expf(-(a0 + __ldg(brgb + 0))));
                    a1 = 1.0f / (1.0f + expf(-(a1 + __ldg(brgb + 1))));
                    a2 = 1.0f / (1.0f + expf(-(a2 + __ldg(brgb + 2))));
                    float* orow = out + ((size_t)tile * MTILE + r) * 3;
                    orow[0] = a0; orow[1] = a1; orow[2] = a2;
                }
                // next tile's first ACT overwrite is layer-0's epilogue, which
                // sits behind layer-0's chunk-0 + pre-epilogue barriers.
            }
        }
    }
}

// ----------------------------------------------------------------------------
extern "C" void kernel_launch(void* const* d_in, const int* in_sizes, int n_in,
                              void* d_out, int out_size) {
    Params P;
    for (int i = 0; i < 32; i++) P.p[i] = (const float*)d_in[i];

    const int B = in_sizes[0] / 63;     // x is [B, 63]
    const int ntiles = B / MTILE;

    // prepass: weights -> fp16 padded row-major layout
    wconv_kernel<<<(WH_TOTAL + 255) / 256, 256>>>(P);

    cudaFuncSetAttribute(nerf_fused_fp16,
                         cudaFuncAttributeMaxDynamicSharedMemorySize, SMEM_TOTAL);

    int nsm = 148;
    cudaDeviceGetAttribute(&nsm, cudaDevAttrMultiProcessorCount, 0);
    int grid = (nsm < ntiles) ? nsm : ntiles;

    nerf_fused_fp16<<<grid, NTHREADS, SMEM_TOTAL>>>(P, (float*)d_out, ntiles, B);
}